// round 1
// baseline (speedup 1.0000x reference)
#include <cuda_runtime.h>
#include <math.h>

#define U_   1024
#define D_   64
#define B_   4096
#define SPB  32       // samples per block

// ---- permuted / masked weight scratch (device globals: no allocs allowed) ----
__device__ float g_W0p[U_ * D_];        // [row j][d]      masked W0, rows sorted by dh
__device__ float g_b0p[U_];
__device__ float g_b1p[U_];
__device__ float g_W1pT[U_ * U_];       // [col c][row r]  masked W1^T (both perm'd)
__device__ float g_W2pT[U_ * 2 * D_];   // [col c][o]      masked W2^T (cols perm'd)

// units sorted by dh = u % 63: dh=v band is contiguous.
// v in [0,15] -> 17 units, v in [16,62] -> 16 units.
// band start: v<=16 ? 17v : 16v+16
__device__ __forceinline__ int perm_of(int j, int& v) {
    int t;
    if (j < 272) { v = j / 17; t = j - v * 17; }
    else         { v = (j - 16) >> 4; t = (j - 16) & 15; }
    return v + 63 * t;   // original unit index
}

// ---- packed fp32x2 helpers (sm_100+) ----
__device__ __forceinline__ unsigned long long pack2(float lo, float hi) {
    unsigned long long r;
    asm("mov.b64 %0, {%1, %2};" : "=l"(r) : "f"(lo), "f"(hi));
    return r;
}
__device__ __forceinline__ void fma_f32x2(unsigned long long& d,
                                          unsigned long long a,
                                          unsigned long long b) {
    asm("fma.rn.f32x2 %0, %1, %2, %0;" : "+l"(d) : "l"(a), "l"(b));
}
__device__ __forceinline__ void unpack2(unsigned long long v, float& lo, float& hi) {
    asm("mov.b64 {%0, %1}, %2;" : "=f"(lo), "=f"(hi) : "l"(v));
}

// ================= prep: permute + mask + transpose weights =================
__global__ void prep_kernel(const float* __restrict__ W0, const float* __restrict__ b0,
                            const float* __restrict__ W1, const float* __restrict__ b1,
                            const float* __restrict__ W2) {
    const int N0 = U_ * D_;        // W0p
    const int N1 = U_;             // b0p
    const int N2 = U_;             // b1p
    const int N3 = U_ * U_;        // W1pT
    const int N4 = U_ * 2 * D_;    // W2pT
    int i = blockIdx.x * blockDim.x + threadIdx.x;
    if (i < N0) {
        int j = i >> 6, d = i & 63, v;
        int pu = perm_of(j, v);
        g_W0p[i] = (d <= v) ? W0[pu * D_ + d] : 0.f;          // m0: d <= dh
    } else if (i < N0 + N1) {
        int j = i - N0, v; int pu = perm_of(j, v);
        g_b0p[j] = b0[pu];
    } else if (i < N0 + N1 + N2) {
        int j = i - N0 - N1, v; int pu = perm_of(j, v);
        g_b1p[j] = b1[pu];
    } else if (i < N0 + N1 + N2 + N3) {
        int k = i - (N0 + N1 + N2);
        int c = k >> 10, r = k & 1023;
        int vc, vr;
        int pc = perm_of(c, vc);
        int pr = perm_of(r, vr);
        g_W1pT[k] = (vr >= vc) ? W1[pr * U_ + pc] : 0.f;      // m1: dh(in) <= dh(out)
    } else if (i < N0 + N1 + N2 + N3 + N4) {
        int k = i - (N0 + N1 + N2 + N3);
        int c = k >> 7, o = k & 127;
        int vc; int pc = perm_of(c, vc);
        g_W2pT[k] = (vc < (o & 63)) ? W2[o * U_ + pc] : 0.f;  // m2: dh < d
    }
}

// ============================= main kernel ==================================
// 128 blocks x 1024 threads; block handles 32 samples through all 64 steps.
// Thread t persistently owns h1-preact accumulator row t (32 samples packed
// as 16 f32x2 registers).
__global__ __launch_bounds__(1024, 1)
void made_kernel(const float* __restrict__ u, const float* __restrict__ b2,
                 float* __restrict__ out) {
    __shared__ __align__(16) float x_sm[D_ * 33];    // x[d][s], padded
    __shared__ __align__(16) float h0b[17 * 32];     // h0 band [c][s]
    __shared__ __align__(16) float h1b[17 * 32];     // h1 band [c][s]
    __shared__ __align__(16) float zsm[128 * 34];    // z accum [o][s], padded even

    const int tid   = threadIdx.x;
    const int lane  = tid & 31;
    const int wid   = tid >> 5;
    const int sbase = blockIdx.x * SPB;

    for (int k = tid; k < 128 * 34; k += 1024) zsm[k] = 0.f;

    unsigned long long acc[16];
#pragma unroll
    for (int k = 0; k < 16; k++) acc[k] = 0ull;

    float ldj = 0.f;
    __syncthreads();

    for (int i = 0; i < D_; i++) {
        if (i > 0) {
            const int v   = i - 1;
            const int s0  = (v <= 16) ? 17 * v : 16 * v + 16;
            const int cnt = (v < 16) ? 17 : 16;

            // ---- Phase A: finalize h0 band (warp = band row, lane = sample)
            if (wid < cnt) {
                const int j = s0 + wid;
                const float* wr = g_W0p + j * D_;
                float a0 = 0.f, a1 = 0.f;
                int d = 0;
                for (; d + 2 <= i; d += 2) {
                    a0 = fmaf(wr[d],     x_sm[d * 33 + lane],       a0);
                    a1 = fmaf(wr[d + 1], x_sm[(d + 1) * 33 + lane], a1);
                }
                if (d < i) a0 = fmaf(wr[d], x_sm[d * 33 + lane], a0);
                h0b[wid * 32 + lane] = fmaxf(g_b0p[j] + a0 + a1, 0.f);
            }
            __syncthreads();

            // ---- Phase B: rank-cnt update of h1 accumulators (the hot loop)
            if (tid >= s0) {
                const float* wcol = g_W1pT + s0 * U_ + tid;
                for (int c = 0; c < cnt; c++, wcol += U_) {
                    const float w = __ldg(wcol);
                    const unsigned long long wp = pack2(w, w);
                    const unsigned long long* hp =
                        (const unsigned long long*)(h0b + c * 32);
#pragma unroll
                    for (int k = 0; k < 16; k++) fma_f32x2(acc[k], wp, hp[k]);
                }
                // ---- Phase C: extract the newly-complete h1 band
                if (tid < s0 + cnt) {
                    const int c = tid - s0;
                    const float b = g_b1p[tid];
#pragma unroll
                    for (int k = 0; k < 16; k++) {
                        float lo, hi; unpack2(acc[k], lo, hi);
                        h1b[c * 32 + 2 * k]     = fmaxf(b + lo, 0.f);
                        h1b[c * 32 + 2 * k + 1] = fmaxf(b + hi, 0.f);
                    }
                }
            }
            __syncthreads();

            // ---- Phase D: scatter band into z accumulators (o = output row)
            if (tid < 512) {
                const int o = tid & 127, kq = tid >> 7;
                unsigned long long* zp =
                    (unsigned long long*)(zsm + o * 34) + kq * 4;
                unsigned long long z0 = zp[0], z1 = zp[1], z2 = zp[2], z3 = zp[3];
                const float* w2c = g_W2pT + s0 * 128 + o;
                for (int c = 0; c < cnt; c++, w2c += 128) {
                    const float w = __ldg(w2c);
                    const unsigned long long wp = pack2(w, w);
                    const unsigned long long* hp =
                        (const unsigned long long*)(h1b + c * 32) + kq * 4;
                    fma_f32x2(z0, wp, hp[0]);
                    fma_f32x2(z1, wp, hp[1]);
                    fma_f32x2(z2, wp, hp[2]);
                    fma_f32x2(z3, wp, hp[3]);
                }
                zp[0] = z0; zp[1] = z1; zp[2] = z2; zp[3] = z3;
            }
            __syncthreads();
        }

        // ---- Phase E: emit x[i], accumulate log-det (lane = sample)
        if (tid < SPB) {
            const float sg = zsm[(64 + i) * 34 + tid] + b2[64 + i];
            const float mu = zsm[i * 34 + tid] + b2[i];
            const float xv = fmaf(u[(sbase + tid) * D_ + i], expf(sg), mu);
            x_sm[i * 33 + tid] = xv;
            ldj += sg;
        }
        __syncthreads();
    }

    // ---- outputs: x [B,64] then ldj [B,1]
    for (int k = tid; k < SPB * D_; k += 1024) {
        const int s = k >> 6, d = k & 63;
        out[(sbase + s) * D_ + d] = x_sm[d * 33 + s];
    }
    if (tid < SPB) out[B_ * D_ + sbase + tid] = ldj;
}

// ============================== launch ======================================
extern "C" void kernel_launch(void* const* d_in, const int* in_sizes, int n_in,
                              void* d_out, int out_size) {
    const float* u  = (const float*)d_in[0];
    const float* W0 = (const float*)d_in[1];
    const float* b0 = (const float*)d_in[2];
    const float* W1 = (const float*)d_in[3];
    const float* b1 = (const float*)d_in[4];
    const float* W2 = (const float*)d_in[5];
    const float* b2 = (const float*)d_in[6];
    float* out = (float*)d_out;

    const int total = U_ * D_ + U_ + U_ + U_ * U_ + U_ * 2 * D_;
    prep_kernel<<<(total + 255) / 256, 256>>>(W0, b0, W1, b1, W2);
    made_kernel<<<B_ / SPB, 1024>>>(u, b2, out);
}